// round 10
// baseline (speedup 1.0000x reference)
#include <cuda_runtime.h>
#include <math.h>
#include <stdint.h>

// Problem constants
#define Bq   4
#define Tq   2048
#define Eq   1024
#define Hq   16
#define Dq   64
#define BHq  (Bq*Hq)

// Scratch (alloc-free rule: static __device__ arrays).
__device__ uint16_t g_Qb [(size_t)BHq * Tq * Dq];  // bf16, d pair-permuted, pre-scaled
__device__ uint16_t g_Kb [(size_t)BHq * Tq * Dq];  // bf16, d pair-permuted
__device__ float    g_V  [(size_t)BHq * Tq * Dq];  // fp32 row-major (exact residual)
__device__ uint16_t g_Vtb[(size_t)BHq * Dq * Tq];  // bf16, transposed, t pair-permuted

#define SCALE_LOG2E 0.18033688011112042f   // 0.125 * log2(e)

// ---- bf16 pack: {lo, hi} -> bf16x2 in one u32 ----
__device__ __forceinline__ uint32_t bf2(float lo, float hi) {
    uint32_t r;
    asm("cvt.rn.bf16x2.f32 %0, %1, %2;" : "=r"(r) : "f"(hi), "f"(lo));
    return r;
}

// split a float2 into bf16x2 hi part and bf16x2 residual (lo) part.
__device__ __forceinline__ void split2(float2 p, uint32_t& hi, uint32_t& lo) {
    hi = bf2(p.x, p.y);
    float h0 = __uint_as_float(hi << 16);
    float h1 = __uint_as_float(hi & 0xffff0000u);
    lo = bf2(p.x - h0, p.y - h1);
}

// ---- warp-level bf16 MMA: D(16x8,f32) += A(16x16,bf16) * B(16x8,bf16) ----
__device__ __forceinline__ void mma_bf16(float c[4], const uint32_t a[4],
                                         uint32_t b0, uint32_t b1) {
    asm volatile(
        "mma.sync.aligned.m16n8k16.row.col.f32.bf16.bf16.f32 "
        "{%0,%1,%2,%3}, {%4,%5,%6,%7}, {%8,%9}, {%0,%1,%2,%3};"
        : "+f"(c[0]), "+f"(c[1]), "+f"(c[2]), "+f"(c[3])
        : "r"(a[0]), "r"(a[1]), "r"(a[2]), "r"(a[3]), "r"(b0), "r"(b1));
}

__device__ __forceinline__ float ex2f(float x) {
    float r; asm("ex2.approx.f32 %0, %1;" : "=f"(r) : "f"(x)); return r;
}
__device__ __forceinline__ uint32_t smem_u32(const void* p) {
    uint32_t a;
    asm("{ .reg .u64 t; cvta.to.shared.u64 t, %1; cvt.u32.u64 %0, t; }" : "=r"(a) : "l"(p));
    return a;
}

#define CP_ASYNC16(dst_u32, src_ptr) \
    asm volatile("cp.async.ca.shared.global [%0], [%1], 16;" :: "r"(dst_u32), "l"(src_ptr) : "memory")
#define CP_COMMIT() asm volatile("cp.async.commit_group;" ::: "memory")
#define CP_WAIT(n)  asm volatile("cp.async.wait_group %0;" :: "n"(n) : "memory")

// ============================================================================
// Kernel 1: tensor-core projections.
//   Q/K: plain bf16 MMA (values are re-rounded to bf16 for attention anyway).
//   V:   error-compensated (xh*Wh + xl*Wh + xh*Wl, err ~2^-18) — the exact
//        residual path. fp32 row-major + bf16 transpose into g_Vtb.
// ============================================================================
#define PT 66   // smem transpose pitch (floats)

__global__ void __launch_bounds__(128) proj_kernel(
    const float* __restrict__ x,
    const float* __restrict__ Wq,
    const float* __restrict__ Wk,
    const float* __restrict__ Wv)
{
    __shared__ float sVt[128 * PT];   // V tile staged for transpose

    const int tid  = threadIdx.x;
    const int lane = tid & 31;
    const int wid  = tid >> 5;
    const int lg   = lane >> 2;
    const int lt   = lane & 3;

    const int bh = blockIdx.y;
    const int b  = bh >> 4;
    const int h  = bh & 15;
    const int t0 = blockIdx.x * 128;
    const int wq = t0 + wid * 32;

    // ---- load x tile as hi/lo bf16 A-fragments (lo used only for V) ----
    uint32_t aXh[2][4][4], aXl[2][4][4];
    #pragma unroll
    for (int mt = 0; mt < 2; ++mt) {
        #pragma unroll
        for (int kj = 0; kj < 4; ++kj) {
            const int r0 = wq + mt * 16 + lg;
            const float* p = x + ((size_t)(b * Tq + r0)) * Eq + h * Dq + kj * 16 + 2 * lt;
            float2 lo0 = *(const float2*)(p);
            float2 hi0 = *(const float2*)(p + 8);
            const float* q = p + (size_t)8 * Eq;
            float2 lo1 = *(const float2*)(q);
            float2 hi1 = *(const float2*)(q + 8);
            split2(lo0, aXh[mt][kj][0], aXl[mt][kj][0]);
            split2(lo1, aXh[mt][kj][1], aXl[mt][kj][1]);
            split2(hi0, aXh[mt][kj][2], aXl[mt][kj][2]);
            split2(hi1, aXh[mt][kj][3], aXl[mt][kj][3]);
        }
    }

    #pragma unroll 1
    for (int m = 0; m < 3; ++m) {
        const float* W = (m == 0) ? Wq : ((m == 1) ? Wk : Wv);

        float c[2][8][4];
        #pragma unroll
        for (int mt = 0; mt < 2; ++mt)
            #pragma unroll
            for (int nt = 0; nt < 8; ++nt)
                #pragma unroll
                for (int e = 0; e < 4; ++e) c[mt][nt][e] = 0.f;

        #pragma unroll
        for (int kj = 0; kj < 4; ++kj) {
            #pragma unroll
            for (int nt = 0; nt < 8; ++nt) {
                const float* wp = W + (size_t)(nt * 8 + lg) * 64 + kj * 16 + 2 * lt;
                if (m < 2) {
                    // Q/K: plain bf16 (result is rounded to bf16 anyway)
                    uint32_t wh0 = bf2(wp[0], wp[1]);
                    uint32_t wh1 = bf2(wp[8], wp[9]);
                    mma_bf16(c[0][nt], aXh[0][kj], wh0, wh1);
                    mma_bf16(c[1][nt], aXh[1][kj], wh0, wh1);
                } else {
                    // V: error-compensated
                    uint32_t wh0, wl0, wh1, wl1;
                    split2(*(const float2*)(wp),     wh0, wl0);
                    split2(*(const float2*)(wp + 8), wh1, wl1);
                    #pragma unroll
                    for (int mt = 0; mt < 2; ++mt) {
                        mma_bf16(c[mt][nt], aXh[mt][kj], wh0, wh1);
                        mma_bf16(c[mt][nt], aXl[mt][kj], wh0, wh1);
                        mma_bf16(c[mt][nt], aXh[mt][kj], wl0, wl1);
                    }
                }
            }
        }

        if (m < 2) {
            // ---- Q/K epilogue: bf16 with pos16 pair-permutation ----
            uint16_t* g = (m == 0 ? g_Qb : g_Kb);
            const float s = (m == 0) ? SCALE_LOG2E : 1.0f;
            #pragma unroll
            for (int mt = 0; mt < 2; ++mt) {
                const int t = wq + mt * 16 + lg;
                uint16_t* r0 = g + ((size_t)bh * Tq + t) * Dq;
                uint16_t* r1 = r0 + (size_t)8 * Dq;
                #pragma unroll
                for (int nt = 0; nt < 8; ++nt) {
                    const int pos = 16 * (nt >> 1) + 4 * lt + 2 * (nt & 1);
                    *(uint32_t*)(r0 + pos) = bf2(c[mt][nt][0] * s, c[mt][nt][1] * s);
                    *(uint32_t*)(r1 + pos) = bf2(c[mt][nt][2] * s, c[mt][nt][3] * s);
                }
            }
        } else {
            // ---- V epilogue: fp32 row-major + smem stage for transpose ----
            #pragma unroll
            for (int mt = 0; mt < 2; ++mt) {
                const int t    = wq + mt * 16 + lg;
                const int tloc = wid * 32 + mt * 16 + lg;
                float* r0 = g_V + ((size_t)bh * Tq + t) * Dq;
                float* r1 = r0 + (size_t)8 * Dq;
                #pragma unroll
                for (int nt = 0; nt < 8; ++nt) {
                    const int col = nt * 8 + 2 * lt;
                    *(float2*)(r0 + col) = make_float2(c[mt][nt][0], c[mt][nt][1]);
                    *(float2*)(r1 + col) = make_float2(c[mt][nt][2], c[mt][nt][3]);
                    *(float2*)(sVt + tloc * PT + col)       = make_float2(c[mt][nt][0], c[mt][nt][1]);
                    *(float2*)(sVt + (tloc + 8) * PT + col) = make_float2(c[mt][nt][2], c[mt][nt][3]);
                }
            }
            __syncthreads();
            const int d    = tid >> 1;
            const int half = tid & 1;
            const float* src = sVt + half * 64 * PT + d;
            uint16_t* dst = g_Vtb + (size_t)bh * Dq * Tq + (size_t)d * Tq + t0 + half * 64;
            #pragma unroll
            for (int blk = 0; blk < 4; ++blk) {
                #pragma unroll
                for (int q = 0; q < 4; ++q) {
                    const float v0 = src[(blk * 16 + 2 * q)     * PT];
                    const float v1 = src[(blk * 16 + 2 * q + 1) * PT];
                    const float v8 = src[(blk * 16 + 2 * q + 8) * PT];
                    const float v9 = src[(blk * 16 + 2 * q + 9) * PT];
                    *(uint2*)(dst + blk * 16 + 4 * q) = make_uint2(bf2(v0, v1), bf2(v8, v9));
                }
            }
        }
    }
}

// ============================================================================
// Kernel 2: mma.sync bf16 flash attention — 3 CTAs/SM edition.
//   CTA = 128 queries; 4 warps x 32 rows. 64-key tiles processed in two
//   32-key halves (score regs 64 -> 32). 3-buffer cp.async ring, staging
//   issued AFTER the barrier so 3 buffers suffice.
// ============================================================================
#define QBLK 128
#define KBLK 64
#define NT   (Tq / KBLK)              // 32 tiles
#define PKB  160                      // byte pitch of K/Vt smem rows
#define TILEB (64 * PKB)              // 10240 B per tile
#define SM_BYTES (6 * TILEB)          // 3 bufs x (K + Vt) = 61440 B

__global__ void __launch_bounds__(128, 3) attn_kernel(float* __restrict__ out)
{
    extern __shared__ __align__(16) char smc[];

    const int tid  = threadIdx.x;
    const int lane = tid & 31;
    const int wid  = tid >> 5;
    const int lg   = lane >> 2;
    const int lt   = lane & 3;

    const int bh = blockIdx.y;
    const int b  = bh >> 4;
    const int h  = bh & 15;
    const int q0 = blockIdx.x * QBLK;
    const int wq = q0 + wid * 32;

    const uint32_t smb = smem_u32(smc);
    const uint16_t* gKb  = g_Kb  + (size_t)bh * Tq * Dq;
    const uint16_t* gVtb = g_Vtb + (size_t)bh * Dq * Tq;

    // ---- Q fragments: m16n8k16 A-frags (32 regs) ----
    uint32_t aQ[2][4][4];
    {
        const uint16_t* Qb = g_Qb + ((size_t)bh * Tq + wq) * Dq;
        #pragma unroll
        for (int mt = 0; mt < 2; ++mt) {
            #pragma unroll
            for (int kj = 0; kj < 4; ++kj) {
                const uint2 lo = *(const uint2*)(Qb + (size_t)(mt * 16 + lg) * Dq + kj * 16 + 4 * lt);
                const uint2 hi = *(const uint2*)(Qb + (size_t)(mt * 16 + lg + 8) * Dq + kj * 16 + 4 * lt);
                aQ[mt][kj][0] = lo.x;
                aQ[mt][kj][1] = hi.x;
                aQ[mt][kj][2] = lo.y;
                aQ[mt][kj][3] = hi.y;
            }
        }
    }

    float o[2][8][4];
    #pragma unroll
    for (int mt = 0; mt < 2; ++mt)
        #pragma unroll
        for (int nt = 0; nt < 8; ++nt)
            #pragma unroll
            for (int e = 0; e < 4; ++e) o[mt][nt][e] = 0.f;

    float rs[4] = {0.f, 0.f, 0.f, 0.f};

    auto stage = [&](int it, int buf) {
        const uint32_t sKu  = smb + (uint32_t)(buf * 2 * TILEB);
        const uint32_t sVtu = sKu + (uint32_t)TILEB;
        const uint16_t* gk = gKb + (size_t)it * KBLK * Dq;
        const int s0 = it * KBLK;
        #pragma unroll
        for (int j = 0; j < 4; ++j) {
            const int f = tid + 128 * j;
            const int r = f >> 3, i = f & 7;
            CP_ASYNC16(sKu + (uint32_t)(r * PKB + 16 * i), gk + (size_t)r * Dq + 8 * i);
            CP_ASYNC16(sVtu + (uint32_t)(r * PKB + 16 * i), gVtb + (size_t)r * Tq + s0 + 8 * i);
        }
    };

    stage(0, 0); CP_COMMIT();
    stage(1, 1); CP_COMMIT();

    int buf = 0;           // buffer of tile `it`
    #pragma unroll 1
    for (int it = 0; it < NT; ++it) {
        if (it + 1 < NT) CP_WAIT(1); else CP_WAIT(0);
        __syncthreads();   // tile `it` visible; all warps done with it-1
        if (it + 2 < NT) {
            int nb = buf + 2; if (nb >= 3) nb -= 3;
            stage(it + 2, nb);
            CP_COMMIT();
        }

        const char* sK  = smc + buf * 2 * TILEB;
        const char* sVt = sK + TILEB;
        if (++buf == 3) buf = 0;

        // ---- two 32-key halves: QK -> exp -> PV (score regs stay at 32) ----
        #pragma unroll
        for (int h2 = 0; h2 < 2; ++h2) {
            float c[2][4][4];
            #pragma unroll
            for (int mt = 0; mt < 2; ++mt)
                #pragma unroll
                for (int nt = 0; nt < 4; ++nt)
                    #pragma unroll
                    for (int e = 0; e < 4; ++e) c[mt][nt][e] = 0.f;

            #pragma unroll
            for (int kj = 0; kj < 4; ++kj) {
                #pragma unroll
                for (int nt = 0; nt < 4; ++nt) {
                    const int s = h2 * 32 + nt * 8 + lg;
                    const uint2 bv = *(const uint2*)(sK + s * PKB + 32 * kj + 8 * lt);
                    mma_bf16(c[0][nt], aQ[0][kj], bv.x, bv.y);
                    mma_bf16(c[1][nt], aQ[1][kj], bv.x, bv.y);
                }
            }

            // exp for P-group j, pipelined ahead of PV(j-1)
            #define EXPP(jj) do { \
                _Pragma("unroll") \
                for (int mt = 0; mt < 2; ++mt) { \
                    _Pragma("unroll") \
                    for (int hh = 0; hh < 2; ++hh) { \
                        float* cc = c[mt][2 * (jj) + hh]; \
                        float p0 = ex2f(cc[0]); \
                        float p1 = ex2f(cc[1]); \
                        float p2 = ex2f(cc[2]); \
                        float p3 = ex2f(cc[3]); \
                        rs[mt * 2 + 0] += p0 + p1; \
                        rs[mt * 2 + 1] += p2 + p3; \
                        cc[0] = p0; cc[1] = p1; cc[2] = p2; cc[3] = p3; \
                    } \
                } \
            } while (0)

            EXPP(0);
            #pragma unroll
            for (int j = 0; j < 2; ++j) {
                if (j < 1) EXPP(1);
                uint32_t aP0[4], aP1[4];
                aP0[0] = bf2(c[0][2*j][0],   c[0][2*j][1]);
                aP0[1] = bf2(c[0][2*j][2],   c[0][2*j][3]);
                aP0[2] = bf2(c[0][2*j+1][0], c[0][2*j+1][1]);
                aP0[3] = bf2(c[0][2*j+1][2], c[0][2*j+1][3]);
                aP1[0] = bf2(c[1][2*j][0],   c[1][2*j][1]);
                aP1[1] = bf2(c[1][2*j][2],   c[1][2*j][3]);
                aP1[2] = bf2(c[1][2*j+1][0], c[1][2*j+1][1]);
                aP1[3] = bf2(c[1][2*j+1][2], c[1][2*j+1][3]);
                const int jj = h2 * 2 + j;    // k16 group within the 64-key tile
                #pragma unroll
                for (int nt = 0; nt < 8; ++nt) {
                    const uint2 bv = *(const uint2*)(sVt + (nt * 8 + lg) * PKB + 32 * jj + 8 * lt);
                    mma_bf16(o[0][nt], aP0, bv.x, bv.y);
                    mma_bf16(o[1][nt], aP1, bv.x, bv.y);
                }
            }
            #undef EXPP
        }
    }

    // ---- row sums ----
    float inv[4];
    #pragma unroll
    for (int i = 0; i < 4; ++i) {
        float v = rs[i];
        v += __shfl_xor_sync(0xffffffffu, v, 1);
        v += __shfl_xor_sync(0xffffffffu, v, 2);
        inv[i] = 1.f / v;
    }

    // ---- epilogue: O/l + V residual (fp32) -> out[b, t, h*64 + d] ----
    #pragma unroll
    for (int mt = 0; mt < 2; ++mt) {
        #pragma unroll
        for (int half = 0; half < 2; ++half) {
            const int t  = wq + mt * 16 + half * 8 + lg;
            const float iv = inv[mt * 2 + half];
            const float2* vr = (const float2*)(g_V + ((size_t)bh * Tq + t) * Dq);
            float2* op = (float2*)(out + ((size_t)(b * Tq + t)) * Eq + h * Dq);
            #pragma unroll
            for (int nt = 0; nt < 8; ++nt) {
                const int idx = nt * 4 + lt;
                float2 v = vr[idx];
                op[idx] = make_float2(o[mt][nt][half * 2 + 0] * iv + v.x,
                                      o[mt][nt][half * 2 + 1] * iv + v.y);
            }
        }
    }
}

// ============================================================================
extern "C" void kernel_launch(void* const* d_in, const int* in_sizes, int n_in,
                              void* d_out, int out_size)
{
    const float* x  = (const float*)d_in[0];
    const float* Wq = (const float*)d_in[1];
    const float* Wk = (const float*)d_in[2];
    const float* Wv = (const float*)d_in[3];
    float* out = (float*)d_out;

    cudaFuncSetAttribute(attn_kernel, cudaFuncAttributeMaxDynamicSharedMemorySize, SM_BYTES);

    dim3 pgrid(Tq / 128, BHq);
    proj_kernel<<<pgrid, 128>>>(x, Wq, Wk, Wv);

    dim3 agrid(Tq / QBLK, BHq);
    attn_kernel<<<agrid, 128, SM_BYTES>>>(out);
}

// round 11
// speedup vs baseline: 1.0986x; 1.0986x over previous
#include <cuda_runtime.h>
#include <math.h>
#include <stdint.h>

// Problem constants
#define Bq   4
#define Tq   2048
#define Eq   1024
#define Hq   16
#define Dq   64
#define BHq  (Bq*Hq)

// Scratch (alloc-free rule: static __device__ arrays).
__device__ uint16_t g_Qb [(size_t)BHq * Tq * Dq];  // bf16, d pair-permuted, pre-scaled
__device__ uint16_t g_Kb [(size_t)BHq * Tq * Dq];  // bf16, d pair-permuted
__device__ float    g_V  [(size_t)BHq * Tq * Dq];  // fp32 row-major (exact residual)
__device__ uint16_t g_Vtb[(size_t)BHq * Dq * Tq];  // bf16, transposed, t pair-permuted

#define SCALE_LOG2E 0.18033688011112042f   // 0.125 * log2(e)

// ---- bf16 pack: {lo, hi} -> bf16x2 in one u32 ----
__device__ __forceinline__ uint32_t bf2(float lo, float hi) {
    uint32_t r;
    asm("cvt.rn.bf16x2.f32 %0, %1, %2;" : "=r"(r) : "f"(hi), "f"(lo));
    return r;
}

// split a float2 into bf16x2 hi part and bf16x2 residual (lo) part.
__device__ __forceinline__ void split2(float2 p, uint32_t& hi, uint32_t& lo) {
    hi = bf2(p.x, p.y);
    float h0 = __uint_as_float(hi << 16);
    float h1 = __uint_as_float(hi & 0xffff0000u);
    lo = bf2(p.x - h0, p.y - h1);
}

// ---- warp-level bf16 MMA: D(16x8,f32) += A(16x16,bf16) * B(16x8,bf16) ----
__device__ __forceinline__ void mma_bf16(float c[4], const uint32_t a[4],
                                         uint32_t b0, uint32_t b1) {
    asm volatile(
        "mma.sync.aligned.m16n8k16.row.col.f32.bf16.bf16.f32 "
        "{%0,%1,%2,%3}, {%4,%5,%6,%7}, {%8,%9}, {%0,%1,%2,%3};"
        : "+f"(c[0]), "+f"(c[1]), "+f"(c[2]), "+f"(c[3])
        : "r"(a[0]), "r"(a[1]), "r"(a[2]), "r"(a[3]), "r"(b0), "r"(b1));
}

__device__ __forceinline__ float ex2f(float x) {
    float r; asm("ex2.approx.f32 %0, %1;" : "=f"(r) : "f"(x)); return r;
}
__device__ __forceinline__ uint32_t smem_u32(const void* p) {
    uint32_t a;
    asm("{ .reg .u64 t; cvta.to.shared.u64 t, %1; cvt.u32.u64 %0, t; }" : "=r"(a) : "l"(p));
    return a;
}

#define CP_ASYNC16(dst_u32, src_ptr) \
    asm volatile("cp.async.ca.shared.global [%0], [%1], 16;" :: "r"(dst_u32), "l"(src_ptr) : "memory")
#define CP_COMMIT() asm volatile("cp.async.commit_group;" ::: "memory")
#define CP_WAIT(n)  asm volatile("cp.async.wait_group %0;" :: "n"(n) : "memory")

// within each 16-block: actual index d stored at position
//   pos = 4*((d&7)>>1) | 2*((d>>3)&1) | (d&1)
__device__ __forceinline__ int pos16(int d) {
    return (d & ~15) | ((((d & 7) >> 1) << 2) | (((d >> 3) & 1) << 1) | (d & 1));
}

// ============================================================================
// Kernel 1: tensor-core projections, error-compensated bf16 (uniform path).
//   W pre-split ONCE per CTA into smem (Wh/Wl per matrix, pos16-permuted,
//   pitch 160B => one LDS.64 per B-frag, conflict-free). Hot loop body is
//   identical for Q/K/V: C = xh*Wh + xl*Wh + xh*Wl  (err ~2^-18).
//   Epilogues: Q/K bf16 pos16-permuted (Q pre-scaled); V fp32 + bf16 transpose.
// ============================================================================
#define PWB   160                      // W smem row pitch (bytes)
#define WPART (64 * PWB)               // 10240 B per W part
#define PT    66                       // sVt transpose pitch (floats)
#define PROJ_SMEM (6 * WPART + 128 * PT * 4)   // 61440 + 33792 = 95232 B

__global__ void __launch_bounds__(128) proj_kernel(
    const float* __restrict__ x,
    const float* __restrict__ Wq,
    const float* __restrict__ Wk,
    const float* __restrict__ Wv)
{
    extern __shared__ __align__(16) char psm[];
    float* sVt = (float*)(psm + 6 * WPART);

    const int tid  = threadIdx.x;
    const int lane = tid & 31;
    const int wid  = tid >> 5;
    const int lg   = lane >> 2;
    const int lt   = lane & 3;

    const int bh = blockIdx.y;
    const int b  = bh >> 4;
    const int h  = bh & 15;
    const int t0 = blockIdx.x * 128;
    const int wq = t0 + wid * 32;

    // ---- pre-split all three W matrices into smem (hi & lo parts) ----
    {
        const int r     = tid >> 1;          // W row (output q), 0..63
        const int halfc = (tid & 1) * 32;    // col half
        #pragma unroll
        for (int m = 0; m < 3; ++m) {
            const float* W = (m == 0) ? Wq : ((m == 1) ? Wk : Wv);
            char* dh = psm + (2 * m)     * WPART + r * PWB;
            char* dl = psm + (2 * m + 1) * WPART + r * PWB;
            #pragma unroll
            for (int j = 0; j < 16; ++j) {
                const int d = halfc + 2 * j;
                float2 w = *(const float2*)(W + (size_t)r * 64 + d);
                uint32_t hi, lo;
                split2(w, hi, lo);
                const int pb = pos16(d) * 2;   // byte offset (pair contiguous)
                *(uint32_t*)(dh + pb) = hi;
                *(uint32_t*)(dl + pb) = lo;
            }
        }
    }

    // ---- load x tile as hi/lo bf16 A-fragments ----
    uint32_t aXh[2][4][4], aXl[2][4][4];
    #pragma unroll
    for (int mt = 0; mt < 2; ++mt) {
        #pragma unroll
        for (int kj = 0; kj < 4; ++kj) {
            const int r0 = wq + mt * 16 + lg;
            const float* p = x + ((size_t)(b * Tq + r0)) * Eq + h * Dq + kj * 16 + 2 * lt;
            float2 lo0 = *(const float2*)(p);
            float2 hi0 = *(const float2*)(p + 8);
            const float* q = p + (size_t)8 * Eq;
            float2 lo1 = *(const float2*)(q);
            float2 hi1 = *(const float2*)(q + 8);
            split2(lo0, aXh[mt][kj][0], aXl[mt][kj][0]);
            split2(lo1, aXh[mt][kj][1], aXl[mt][kj][1]);
            split2(hi0, aXh[mt][kj][2], aXl[mt][kj][2]);
            split2(hi1, aXh[mt][kj][3], aXl[mt][kj][3]);
        }
    }
    __syncthreads();   // W parts staged

    #pragma unroll 1
    for (int m = 0; m < 3; ++m) {
        const char* sWh = psm + (2 * m)     * WPART;
        const char* sWl = psm + (2 * m + 1) * WPART;

        float c[2][8][4];
        #pragma unroll
        for (int mt = 0; mt < 2; ++mt)
            #pragma unroll
            for (int nt = 0; nt < 8; ++nt)
                #pragma unroll
                for (int e = 0; e < 4; ++e) c[mt][nt][e] = 0.f;

        // uniform hot loop (identical body for all m)
        #pragma unroll
        for (int kj = 0; kj < 4; ++kj) {
            #pragma unroll
            for (int nt = 0; nt < 8; ++nt) {
                const int off = (nt * 8 + lg) * PWB + kj * 32 + lt * 8;
                const uint2 wh = *(const uint2*)(sWh + off);
                const uint2 wl = *(const uint2*)(sWl + off);
                #pragma unroll
                for (int mt = 0; mt < 2; ++mt) {
                    mma_bf16(c[mt][nt], aXh[mt][kj], wh.x, wh.y);   // hi*hi
                    mma_bf16(c[mt][nt], aXl[mt][kj], wh.x, wh.y);   // lo*hi
                    mma_bf16(c[mt][nt], aXh[mt][kj], wl.x, wl.y);   // hi*lo
                }
            }
        }

        if (m < 2) {
            // ---- Q/K epilogue: bf16 with pos16 pair-permutation ----
            uint16_t* g = (m == 0 ? g_Qb : g_Kb);
            const float s = (m == 0) ? SCALE_LOG2E : 1.0f;
            #pragma unroll
            for (int mt = 0; mt < 2; ++mt) {
                const int t = wq + mt * 16 + lg;
                uint16_t* r0 = g + ((size_t)bh * Tq + t) * Dq;
                uint16_t* r1 = r0 + (size_t)8 * Dq;
                #pragma unroll
                for (int nt = 0; nt < 8; ++nt) {
                    const int pos = 16 * (nt >> 1) + 4 * lt + 2 * (nt & 1);
                    *(uint32_t*)(r0 + pos) = bf2(c[mt][nt][0] * s, c[mt][nt][1] * s);
                    *(uint32_t*)(r1 + pos) = bf2(c[mt][nt][2] * s, c[mt][nt][3] * s);
                }
            }
        } else {
            // ---- V epilogue: fp32 row-major + smem stage for transpose ----
            #pragma unroll
            for (int mt = 0; mt < 2; ++mt) {
                const int t    = wq + mt * 16 + lg;
                const int tloc = wid * 32 + mt * 16 + lg;
                float* r0 = g_V + ((size_t)bh * Tq + t) * Dq;
                float* r1 = r0 + (size_t)8 * Dq;
                #pragma unroll
                for (int nt = 0; nt < 8; ++nt) {
                    const int col = nt * 8 + 2 * lt;
                    *(float2*)(r0 + col) = make_float2(c[mt][nt][0], c[mt][nt][1]);
                    *(float2*)(r1 + col) = make_float2(c[mt][nt][2], c[mt][nt][3]);
                    *(float2*)(sVt + tloc * PT + col)       = make_float2(c[mt][nt][0], c[mt][nt][1]);
                    *(float2*)(sVt + (tloc + 8) * PT + col) = make_float2(c[mt][nt][2], c[mt][nt][3]);
                }
            }
            __syncthreads();
            const int d    = tid >> 1;
            const int half = tid & 1;
            const float* src = sVt + half * 64 * PT + d;
            uint16_t* dst = g_Vtb + (size_t)bh * Dq * Tq + (size_t)d * Tq + t0 + half * 64;
            #pragma unroll
            for (int blk = 0; blk < 4; ++blk) {
                #pragma unroll
                for (int q = 0; q < 4; ++q) {
                    const float v0 = src[(blk * 16 + 2 * q)     * PT];
                    const float v1 = src[(blk * 16 + 2 * q + 1) * PT];
                    const float v8 = src[(blk * 16 + 2 * q + 8) * PT];
                    const float v9 = src[(blk * 16 + 2 * q + 9) * PT];
                    *(uint2*)(dst + blk * 16 + 4 * q) = make_uint2(bf2(v0, v1), bf2(v8, v9));
                }
            }
        }
    }
}

// ============================================================================
// Kernel 2: mma.sync bf16 flash attention (revert to R9 — proven 186us).
//   CTA = 128 queries; 4 warps x 32 rows; 2 CTAs/SM. K-tiles of 64,
//   4-buffer cp.async ring. P stays in registers (cvt C-frag -> bf16 A-frag).
// ============================================================================
#define QBLK 128
#define KBLK 64
#define NT   (Tq / KBLK)              // 32 tiles
#define PKB  160                      // byte pitch of K/Vt smem rows
#define TILEB (64 * PKB)              // 10240 B per tile
#define SM_BYTES (8 * TILEB)          // 4 bufs x (K + Vt) = 81920 B

__global__ void __launch_bounds__(128, 2) attn_kernel(float* __restrict__ out)
{
    extern __shared__ __align__(16) char smc[];

    const int tid  = threadIdx.x;
    const int lane = tid & 31;
    const int wid  = tid >> 5;
    const int lg   = lane >> 2;
    const int lt   = lane & 3;

    const int bh = blockIdx.y;
    const int b  = bh >> 4;
    const int h  = bh & 15;
    const int q0 = blockIdx.x * QBLK;
    const int wq = q0 + wid * 32;

    const uint32_t smb = smem_u32(smc);
    const uint16_t* gKb  = g_Kb  + (size_t)bh * Tq * Dq;
    const uint16_t* gVtb = g_Vtb + (size_t)bh * Dq * Tq;

    // ---- Q fragments: m16n8k16 A-frags ----
    uint32_t aQ[2][4][4];
    {
        const uint16_t* Qb = g_Qb + ((size_t)bh * Tq + wq) * Dq;
        #pragma unroll
        for (int mt = 0; mt < 2; ++mt) {
            #pragma unroll
            for (int kj = 0; kj < 4; ++kj) {
                const uint2 lo = *(const uint2*)(Qb + (size_t)(mt * 16 + lg) * Dq + kj * 16 + 4 * lt);
                const uint2 hi = *(const uint2*)(Qb + (size_t)(mt * 16 + lg + 8) * Dq + kj * 16 + 4 * lt);
                aQ[mt][kj][0] = lo.x;
                aQ[mt][kj][1] = hi.x;
                aQ[mt][kj][2] = lo.y;
                aQ[mt][kj][3] = hi.y;
            }
        }
    }

    float o[2][8][4];
    #pragma unroll
    for (int mt = 0; mt < 2; ++mt)
        #pragma unroll
        for (int nt = 0; nt < 8; ++nt)
            #pragma unroll
            for (int e = 0; e < 4; ++e) o[mt][nt][e] = 0.f;

    float rs[4] = {0.f, 0.f, 0.f, 0.f};

    auto stage = [&](int it, int buf) {
        const uint32_t sKu  = smb + (uint32_t)(buf * 2 * TILEB);
        const uint32_t sVtu = sKu + (uint32_t)TILEB;
        const uint16_t* gk = gKb + (size_t)it * KBLK * Dq;
        const int s0 = it * KBLK;
        #pragma unroll
        for (int j = 0; j < 4; ++j) {
            const int f = tid + 128 * j;
            const int r = f >> 3, i = f & 7;
            CP_ASYNC16(sKu + (uint32_t)(r * PKB + 16 * i), gk + (size_t)r * Dq + 8 * i);
            CP_ASYNC16(sVtu + (uint32_t)(r * PKB + 16 * i), gVtb + (size_t)r * Tq + s0 + 8 * i);
        }
    };

    stage(0, 0); CP_COMMIT();
    stage(1, 1); CP_COMMIT();

    #pragma unroll 1
    for (int it = 0; it < NT; ++it) {
        if (it + 2 < NT) {
            stage(it + 2, (it + 2) & 3);
            CP_COMMIT();
            CP_WAIT(2);
        } else if (it + 1 < NT) {
            CP_WAIT(1);
        } else {
            CP_WAIT(0);
        }
        __syncthreads();

        const char* sK  = smc + (it & 3) * 2 * TILEB;
        const char* sVt = sK + TILEB;

        // ---- QK^T ----
        float c[2][8][4];
        #pragma unroll
        for (int mt = 0; mt < 2; ++mt)
            #pragma unroll
            for (int nt = 0; nt < 8; ++nt)
                #pragma unroll
                for (int e = 0; e < 4; ++e) c[mt][nt][e] = 0.f;

        #pragma unroll
        for (int kj = 0; kj < 4; ++kj) {
            #pragma unroll
            for (int nt = 0; nt < 8; ++nt) {
                const uint2 bv = *(const uint2*)(sK + (nt * 8 + lg) * PKB + 32 * kj + 8 * lt);
                mma_bf16(c[0][nt], aQ[0][kj], bv.x, bv.y);
                mma_bf16(c[1][nt], aQ[1][kj], bv.x, bv.y);
            }
        }

        // ---- exp (pipelined into PV) + PV ----
        #define EXPP(jj) do { \
            _Pragma("unroll") \
            for (int mt = 0; mt < 2; ++mt) { \
                _Pragma("unroll") \
                for (int hh = 0; hh < 2; ++hh) { \
                    float* cc = c[mt][2 * (jj) + hh]; \
                    float p0 = ex2f(cc[0]); \
                    float p1 = ex2f(cc[1]); \
                    float p2 = ex2f(cc[2]); \
                    float p3 = ex2f(cc[3]); \
                    rs[mt * 2 + 0] += p0 + p1; \
                    rs[mt * 2 + 1] += p2 + p3; \
                    cc[0] = p0; cc[1] = p1; cc[2] = p2; cc[3] = p3; \
                } \
            } \
        } while (0)

        EXPP(0);
        #pragma unroll
        for (int j = 0; j < 4; ++j) {
            if (j < 3) EXPP(j + 1);
            uint32_t aP0[4], aP1[4];
            aP0[0] = bf2(c[0][2*j][0],   c[0][2*j][1]);
            aP0[1] = bf2(c[0][2*j][2],   c[0][2*j][3]);
            aP0[2] = bf2(c[0][2*j+1][0], c[0][2*j+1][1]);
            aP0[3] = bf2(c[0][2*j+1][2], c[0][2*j+1][3]);
            aP1[0] = bf2(c[1][2*j][0],   c[1][2*j][1]);
            aP1[1] = bf2(c[1][2*j][2],   c[1][2*j][3]);
            aP1[2] = bf2(c[1][2*j+1][0], c[1][2*j+1][1]);
            aP1[3] = bf2(c[1][2*j+1][2], c[1][2*j+1][3]);
            #pragma unroll
            for (int nt = 0; nt < 8; ++nt) {
                const uint2 bv = *(const uint2*)(sVt + (nt * 8 + lg) * PKB + 32 * j + 8 * lt);
                mma_bf16(o[0][nt], aP0, bv.x, bv.y);
                mma_bf16(o[1][nt], aP1, bv.x, bv.y);
            }
        }
        #undef EXPP
    }

    // ---- row sums ----
    float inv[4];
    #pragma unroll
    for (int i = 0; i < 4; ++i) {
        float v = rs[i];
        v += __shfl_xor_sync(0xffffffffu, v, 1);
        v += __shfl_xor_sync(0xffffffffu, v, 2);
        inv[i] = 1.f / v;
    }

    // ---- epilogue: O/l + V residual (fp32) -> out[b, t, h*64 + d] ----
    #pragma unroll
    for (int mt = 0; mt < 2; ++mt) {
        #pragma unroll
        for (int half = 0; half < 2; ++half) {
            const int t  = wq + mt * 16 + half * 8 + lg;
            const float iv = inv[mt * 2 + half];
            const float2* vr = (const float2*)(g_V + ((size_t)bh * Tq + t) * Dq);
            float2* op = (float2*)(out + ((size_t)(b * Tq + t)) * Eq + h * Dq);
            #pragma unroll
            for (int nt = 0; nt < 8; ++nt) {
                const int idx = nt * 4 + lt;
                float2 v = vr[idx];
                op[idx] = make_float2(o[mt][nt][half * 2 + 0] * iv + v.x,
                                      o[mt][nt][half * 2 + 1] * iv + v.y);
            }
        }
    }
}

// ============================================================================
extern "C" void kernel_launch(void* const* d_in, const int* in_sizes, int n_in,
                              void* d_out, int out_size)
{
    const float* x  = (const float*)d_in[0];
    const float* Wq = (const float*)d_in[1];
    const float* Wk = (const float*)d_in[2];
    const float* Wv = (const float*)d_in[3];
    float* out = (float*)d_out;

    cudaFuncSetAttribute(proj_kernel, cudaFuncAttributeMaxDynamicSharedMemorySize, PROJ_SMEM);
    cudaFuncSetAttribute(attn_kernel, cudaFuncAttributeMaxDynamicSharedMemorySize, SM_BYTES);

    dim3 pgrid(Tq / 128, BHq);
    proj_kernel<<<pgrid, 128, PROJ_SMEM>>>(x, Wq, Wk, Wv);

    dim3 agrid(Tq / QBLK, BHq);
    attn_kernel<<<agrid, 128, SM_BYTES>>>(out);
}

// round 12
// speedup vs baseline: 1.1076x; 1.0082x over previous
#include <cuda_runtime.h>
#include <math.h>
#include <stdint.h>

// Problem constants
#define Bq   4
#define Tq   2048
#define Eq   1024
#define Hq   16
#define Dq   64
#define BHq  (Bq*Hq)

// Scratch (alloc-free rule: static __device__ arrays).
__device__ uint16_t g_Qb [(size_t)BHq * Tq * Dq];  // bf16, d pair-permuted, pre-scaled
__device__ uint16_t g_Kb [(size_t)BHq * Tq * Dq];  // bf16, d pair-permuted
__device__ float    g_V  [(size_t)BHq * Tq * Dq];  // fp32 row-major (exact residual)
__device__ uint16_t g_Vtb[(size_t)BHq * Dq * Tq];  // bf16, transposed, t pair-permuted

#define SCALE_LOG2E 0.18033688011112042f   // 0.125 * log2(e)

// ---- bf16 pack: {lo, hi} -> bf16x2 in one u32 ----
__device__ __forceinline__ uint32_t bf2(float lo, float hi) {
    uint32_t r;
    asm("cvt.rn.bf16x2.f32 %0, %1, %2;" : "=r"(r) : "f"(hi), "f"(lo));
    return r;
}

// split a float2 into bf16x2 hi part and bf16x2 residual (lo) part.
__device__ __forceinline__ void split2(float2 p, uint32_t& hi, uint32_t& lo) {
    hi = bf2(p.x, p.y);
    float h0 = __uint_as_float(hi << 16);
    float h1 = __uint_as_float(hi & 0xffff0000u);
    lo = bf2(p.x - h0, p.y - h1);
}

// ---- warp-level bf16 MMA: D(16x8,f32) += A(16x16,bf16) * B(16x8,bf16) ----
__device__ __forceinline__ void mma_bf16(float c[4], const uint32_t a[4],
                                         uint32_t b0, uint32_t b1) {
    asm volatile(
        "mma.sync.aligned.m16n8k16.row.col.f32.bf16.bf16.f32 "
        "{%0,%1,%2,%3}, {%4,%5,%6,%7}, {%8,%9}, {%0,%1,%2,%3};"
        : "+f"(c[0]), "+f"(c[1]), "+f"(c[2]), "+f"(c[3])
        : "r"(a[0]), "r"(a[1]), "r"(a[2]), "r"(a[3]), "r"(b0), "r"(b1));
}

__device__ __forceinline__ float ex2f(float x) {
    float r; asm("ex2.approx.f32 %0, %1;" : "=f"(r) : "f"(x)); return r;
}
__device__ __forceinline__ uint32_t smem_u32(const void* p) {
    uint32_t a;
    asm("{ .reg .u64 t; cvta.to.shared.u64 t, %1; cvt.u32.u64 %0, t; }" : "=r"(a) : "l"(p));
    return a;
}

#define CP_ASYNC16(dst_u32, src_ptr) \
    asm volatile("cp.async.ca.shared.global [%0], [%1], 16;" :: "r"(dst_u32), "l"(src_ptr) : "memory")
#define CP_COMMIT() asm volatile("cp.async.commit_group;" ::: "memory")
#define CP_WAIT(n)  asm volatile("cp.async.wait_group %0;" :: "n"(n) : "memory")

// ============================================================================
// Kernel 1: tensor-core projections (occupancy edition).
//   Q/K: plain bf16 MMA, branchless uniform loop per matrix (results are
//        rounded to bf16 for the attention kernel anyway; costs ~2e-4 rel).
//   V:   error-compensated (xh*Wh + xl*Wh + xh*Wl, err ~2^-18) — the exact
//        residual path. fp32 row-major + bf16 transpose into g_Vtb.
//   __launch_bounds__(128, 3): ~170-reg cap => 3 CTAs/SM, 12 resident warps.
// ============================================================================
#define PT 66   // smem transpose pitch (floats)

__global__ void __launch_bounds__(128, 3) proj_kernel(
    const float* __restrict__ x,
    const float* __restrict__ Wq,
    const float* __restrict__ Wk,
    const float* __restrict__ Wv)
{
    __shared__ float sVt[128 * PT];   // 33792 B static

    const int tid  = threadIdx.x;
    const int lane = tid & 31;
    const int wid  = tid >> 5;
    const int lg   = lane >> 2;
    const int lt   = lane & 3;

    const int bh = blockIdx.y;
    const int b  = bh >> 4;
    const int h  = bh & 15;
    const int t0 = blockIdx.x * 128;
    const int wq = t0 + wid * 32;

    // ---- load x tile as hi/lo bf16 A-fragments (lo used only for V) ----
    uint32_t aXh[2][4][4], aXl[2][4][4];
    #pragma unroll
    for (int mt = 0; mt < 2; ++mt) {
        #pragma unroll
        for (int kj = 0; kj < 4; ++kj) {
            const int r0 = wq + mt * 16 + lg;
            const float* p = x + ((size_t)(b * Tq + r0)) * Eq + h * Dq + kj * 16 + 2 * lt;
            float2 lo0 = *(const float2*)(p);
            float2 hi0 = *(const float2*)(p + 8);
            const float* q = p + (size_t)8 * Eq;
            float2 lo1 = *(const float2*)(q);
            float2 hi1 = *(const float2*)(q + 8);
            split2(lo0, aXh[mt][kj][0], aXl[mt][kj][0]);
            split2(lo1, aXh[mt][kj][1], aXl[mt][kj][1]);
            split2(hi0, aXh[mt][kj][2], aXl[mt][kj][2]);
            split2(hi1, aXh[mt][kj][3], aXl[mt][kj][3]);
        }
    }

    // ================= Q and K: plain bf16, uniform branchless loops ========
    #pragma unroll 1
    for (int m = 0; m < 2; ++m) {
        const float* W = (m == 0) ? Wq : Wk;

        float c[2][8][4];
        #pragma unroll
        for (int mt = 0; mt < 2; ++mt)
            #pragma unroll
            for (int nt = 0; nt < 8; ++nt)
                #pragma unroll
                for (int e = 0; e < 4; ++e) c[mt][nt][e] = 0.f;

        #pragma unroll
        for (int kj = 0; kj < 4; ++kj) {
            #pragma unroll
            for (int nt = 0; nt < 8; ++nt) {
                const float* wp = W + (size_t)(nt * 8 + lg) * 64 + kj * 16 + 2 * lt;
                const uint32_t wh0 = bf2(wp[0], wp[1]);
                const uint32_t wh1 = bf2(wp[8], wp[9]);
                mma_bf16(c[0][nt], aXh[0][kj], wh0, wh1);
                mma_bf16(c[1][nt], aXh[1][kj], wh0, wh1);
            }
        }

        // ---- epilogue: bf16 with pos16 pair-permutation ----
        uint16_t* g = (m == 0 ? g_Qb : g_Kb);
        const float s = (m == 0) ? SCALE_LOG2E : 1.0f;
        #pragma unroll
        for (int mt = 0; mt < 2; ++mt) {
            const int t = wq + mt * 16 + lg;
            uint16_t* r0 = g + ((size_t)bh * Tq + t) * Dq;
            uint16_t* r1 = r0 + (size_t)8 * Dq;
            #pragma unroll
            for (int nt = 0; nt < 8; ++nt) {
                const int pos = 16 * (nt >> 1) + 4 * lt + 2 * (nt & 1);
                *(uint32_t*)(r0 + pos) = bf2(c[mt][nt][0] * s, c[mt][nt][1] * s);
                *(uint32_t*)(r1 + pos) = bf2(c[mt][nt][2] * s, c[mt][nt][3] * s);
            }
        }
    }

    // ================= V: error-compensated =================================
    {
        float c[2][8][4];
        #pragma unroll
        for (int mt = 0; mt < 2; ++mt)
            #pragma unroll
            for (int nt = 0; nt < 8; ++nt)
                #pragma unroll
                for (int e = 0; e < 4; ++e) c[mt][nt][e] = 0.f;

        #pragma unroll
        for (int kj = 0; kj < 4; ++kj) {
            #pragma unroll
            for (int nt = 0; nt < 8; ++nt) {
                const float* wp = Wv + (size_t)(nt * 8 + lg) * 64 + kj * 16 + 2 * lt;
                uint32_t wh0, wl0, wh1, wl1;
                split2(*(const float2*)(wp),     wh0, wl0);
                split2(*(const float2*)(wp + 8), wh1, wl1);
                #pragma unroll
                for (int mt = 0; mt < 2; ++mt) {
                    mma_bf16(c[mt][nt], aXh[mt][kj], wh0, wh1);
                    mma_bf16(c[mt][nt], aXl[mt][kj], wh0, wh1);
                    mma_bf16(c[mt][nt], aXh[mt][kj], wl0, wl1);
                }
            }
        }

        // ---- V epilogue: fp32 row-major + smem stage for transpose ----
        #pragma unroll
        for (int mt = 0; mt < 2; ++mt) {
            const int t    = wq + mt * 16 + lg;
            const int tloc = wid * 32 + mt * 16 + lg;
            float* r0 = g_V + ((size_t)bh * Tq + t) * Dq;
            float* r1 = r0 + (size_t)8 * Dq;
            #pragma unroll
            for (int nt = 0; nt < 8; ++nt) {
                const int col = nt * 8 + 2 * lt;
                *(float2*)(r0 + col) = make_float2(c[mt][nt][0], c[mt][nt][1]);
                *(float2*)(r1 + col) = make_float2(c[mt][nt][2], c[mt][nt][3]);
                *(float2*)(sVt + tloc * PT + col)       = make_float2(c[mt][nt][0], c[mt][nt][1]);
                *(float2*)(sVt + (tloc + 8) * PT + col) = make_float2(c[mt][nt][2], c[mt][nt][3]);
            }
        }
        __syncthreads();
        const int d    = tid >> 1;
        const int half = tid & 1;
        const float* src = sVt + half * 64 * PT + d;
        uint16_t* dst = g_Vtb + (size_t)bh * Dq * Tq + (size_t)d * Tq + t0 + half * 64;
        #pragma unroll
        for (int blk = 0; blk < 4; ++blk) {
            #pragma unroll
            for (int q = 0; q < 4; ++q) {
                const float v0 = src[(blk * 16 + 2 * q)     * PT];
                const float v1 = src[(blk * 16 + 2 * q + 1) * PT];
                const float v8 = src[(blk * 16 + 2 * q + 8) * PT];
                const float v9 = src[(blk * 16 + 2 * q + 9) * PT];
                *(uint2*)(dst + blk * 16 + 4 * q) = make_uint2(bf2(v0, v1), bf2(v8, v9));
            }
        }
    }
}

// ============================================================================
// Kernel 2: mma.sync bf16 flash attention (R9 — proven 185us, UNCHANGED).
//   CTA = 128 queries; 4 warps x 32 rows; 2 CTAs/SM. K-tiles of 64,
//   4-buffer cp.async ring. P stays in registers (cvt C-frag -> bf16 A-frag).
// ============================================================================
#define QBLK 128
#define KBLK 64
#define NT   (Tq / KBLK)              // 32 tiles
#define PKB  160                      // byte pitch of K/Vt smem rows
#define TILEB (64 * PKB)              // 10240 B per tile
#define SM_BYTES (8 * TILEB)          // 4 bufs x (K + Vt) = 81920 B

__global__ void __launch_bounds__(128, 2) attn_kernel(float* __restrict__ out)
{
    extern __shared__ __align__(16) char smc[];

    const int tid  = threadIdx.x;
    const int lane = tid & 31;
    const int wid  = tid >> 5;
    const int lg   = lane >> 2;
    const int lt   = lane & 3;

    const int bh = blockIdx.y;
    const int b  = bh >> 4;
    const int h  = bh & 15;
    const int q0 = blockIdx.x * QBLK;
    const int wq = q0 + wid * 32;

    const uint32_t smb = smem_u32(smc);
    const uint16_t* gKb  = g_Kb  + (size_t)bh * Tq * Dq;
    const uint16_t* gVtb = g_Vtb + (size_t)bh * Dq * Tq;

    // ---- Q fragments: m16n8k16 A-frags ----
    uint32_t aQ[2][4][4];
    {
        const uint16_t* Qb = g_Qb + ((size_t)bh * Tq + wq) * Dq;
        #pragma unroll
        for (int mt = 0; mt < 2; ++mt) {
            #pragma unroll
            for (int kj = 0; kj < 4; ++kj) {
                const uint2 lo = *(const uint2*)(Qb + (size_t)(mt * 16 + lg) * Dq + kj * 16 + 4 * lt);
                const uint2 hi = *(const uint2*)(Qb + (size_t)(mt * 16 + lg + 8) * Dq + kj * 16 + 4 * lt);
                aQ[mt][kj][0] = lo.x;
                aQ[mt][kj][1] = hi.x;
                aQ[mt][kj][2] = lo.y;
                aQ[mt][kj][3] = hi.y;
            }
        }
    }

    float o[2][8][4];
    #pragma unroll
    for (int mt = 0; mt < 2; ++mt)
        #pragma unroll
        for (int nt = 0; nt < 8; ++nt)
            #pragma unroll
            for (int e = 0; e < 4; ++e) o[mt][nt][e] = 0.f;

    float rs[4] = {0.f, 0.f, 0.f, 0.f};

    auto stage = [&](int it, int buf) {
        const uint32_t sKu  = smb + (uint32_t)(buf * 2 * TILEB);
        const uint32_t sVtu = sKu + (uint32_t)TILEB;
        const uint16_t* gk = gKb + (size_t)it * KBLK * Dq;
        const int s0 = it * KBLK;
        #pragma unroll
        for (int j = 0; j < 4; ++j) {
            const int f = tid + 128 * j;
            const int r = f >> 3, i = f & 7;
            CP_ASYNC16(sKu + (uint32_t)(r * PKB + 16 * i), gk + (size_t)r * Dq + 8 * i);
            CP_ASYNC16(sVtu + (uint32_t)(r * PKB + 16 * i), gVtb + (size_t)r * Tq + s0 + 8 * i);
        }
    };

    stage(0, 0); CP_COMMIT();
    stage(1, 1); CP_COMMIT();

    #pragma unroll 1
    for (int it = 0; it < NT; ++it) {
        if (it + 2 < NT) {
            stage(it + 2, (it + 2) & 3);
            CP_COMMIT();
            CP_WAIT(2);
        } else if (it + 1 < NT) {
            CP_WAIT(1);
        } else {
            CP_WAIT(0);
        }
        __syncthreads();

        const char* sK  = smc + (it & 3) * 2 * TILEB;
        const char* sVt = sK + TILEB;

        // ---- QK^T ----
        float c[2][8][4];
        #pragma unroll
        for (int mt = 0; mt < 2; ++mt)
            #pragma unroll
            for (int nt = 0; nt < 8; ++nt)
                #pragma unroll
                for (int e = 0; e < 4; ++e) c[mt][nt][e] = 0.f;

        #pragma unroll
        for (int kj = 0; kj < 4; ++kj) {
            #pragma unroll
            for (int nt = 0; nt < 8; ++nt) {
                const uint2 bv = *(const uint2*)(sK + (nt * 8 + lg) * PKB + 32 * kj + 8 * lt);
                mma_bf16(c[0][nt], aQ[0][kj], bv.x, bv.y);
                mma_bf16(c[1][nt], aQ[1][kj], bv.x, bv.y);
            }
        }

        // ---- exp (pipelined into PV) + PV ----
        #define EXPP(jj) do { \
            _Pragma("unroll") \
            for (int mt = 0; mt < 2; ++mt) { \
                _Pragma("unroll") \
                for (int hh = 0; hh < 2; ++hh) { \
                    float* cc = c[mt][2 * (jj) + hh]; \
                    float p0 = ex2f(cc[0]); \
                    float p1 = ex2f(cc[1]); \
                    float p2 = ex2f(cc[2]); \
                    float p3 = ex2f(cc[3]); \
                    rs[mt * 2 + 0] += p0 + p1; \
                    rs[mt * 2 + 1] += p2 + p3; \
                    cc[0] = p0; cc[1] = p1; cc[2] = p2; cc[3] = p3; \
                } \
            } \
        } while (0)

        EXPP(0);
        #pragma unroll
        for (int j = 0; j < 4; ++j) {
            if (j < 3) EXPP(j + 1);
            uint32_t aP0[4], aP1[4];
            aP0[0] = bf2(c[0][2*j][0],   c[0][2*j][1]);
            aP0[1] = bf2(c[0][2*j][2],   c[0][2*j][3]);
            aP0[2] = bf2(c[0][2*j+1][0], c[0][2*j+1][1]);
            aP0[3] = bf2(c[0][2*j+1][2], c[0][2*j+1][3]);
            aP1[0] = bf2(c[1][2*j][0],   c[1][2*j][1]);
            aP1[1] = bf2(c[1][2*j][2],   c[1][2*j][3]);
            aP1[2] = bf2(c[1][2*j+1][0], c[1][2*j+1][1]);
            aP1[3] = bf2(c[1][2*j+1][2], c[1][2*j+1][3]);
            #pragma unroll
            for (int nt = 0; nt < 8; ++nt) {
                const uint2 bv = *(const uint2*)(sVt + (nt * 8 + lg) * PKB + 32 * j + 8 * lt);
                mma_bf16(o[0][nt], aP0, bv.x, bv.y);
                mma_bf16(o[1][nt], aP1, bv.x, bv.y);
            }
        }
        #undef EXPP
    }

    // ---- row sums ----
    float inv[4];
    #pragma unroll
    for (int i = 0; i < 4; ++i) {
        float v = rs[i];
        v += __shfl_xor_sync(0xffffffffu, v, 1);
        v += __shfl_xor_sync(0xffffffffu, v, 2);
        inv[i] = 1.f / v;
    }

    // ---- epilogue: O/l + V residual (fp32) -> out[b, t, h*64 + d] ----
    #pragma unroll
    for (int mt = 0; mt < 2; ++mt) {
        #pragma unroll
        for (int half = 0; half < 2; ++half) {
            const int t  = wq + mt * 16 + half * 8 + lg;
            const float iv = inv[mt * 2 + half];
            const float2* vr = (const float2*)(g_V + ((size_t)bh * Tq + t) * Dq);
            float2* op = (float2*)(out + ((size_t)(b * Tq + t)) * Eq + h * Dq);
            #pragma unroll
            for (int nt = 0; nt < 8; ++nt) {
                const int idx = nt * 4 + lt;
                float2 v = vr[idx];
                op[idx] = make_float2(o[mt][nt][half * 2 + 0] * iv + v.x,
                                      o[mt][nt][half * 2 + 1] * iv + v.y);
            }
        }
    }
}

// ============================================================================
extern "C" void kernel_launch(void* const* d_in, const int* in_sizes, int n_in,
                              void* d_out, int out_size)
{
    const float* x  = (const float*)d_in[0];
    const float* Wq = (const float*)d_in[1];
    const float* Wk = (const float*)d_in[2];
    const float* Wv = (const float*)d_in[3];
    float* out = (float*)d_out;

    cudaFuncSetAttribute(attn_kernel, cudaFuncAttributeMaxDynamicSharedMemorySize, SM_BYTES);

    dim3 pgrid(Tq / 128, BHq);
    proj_kernel<<<pgrid, 128>>>(x, Wq, Wk, Wv);

    dim3 agrid(Tq / QBLK, BHq);
    attn_kernel<<<agrid, 128, SM_BYTES>>>(out);
}

// round 13
// speedup vs baseline: 1.1122x; 1.0042x over previous
#include <cuda_runtime.h>
#include <math.h>
#include <stdint.h>

// Problem constants
#define Bq   4
#define Tq   2048
#define Eq   1024
#define Hq   16
#define Dq   64
#define BHq  (Bq*Hq)

// Scratch (alloc-free rule: static __device__ arrays).
__device__ uint16_t g_Qb [(size_t)BHq * Tq * Dq];  // bf16, d pair-permuted, pre-scaled
__device__ uint16_t g_Kb [(size_t)BHq * Tq * Dq];  // bf16, d pair-permuted
__device__ float    g_V  [(size_t)BHq * Tq * Dq];  // fp32 row-major (exact residual)
__device__ uint16_t g_Vtb[(size_t)BHq * Dq * Tq];  // bf16, transposed, t pair-permuted

#define SCALE_LOG2E 0.18033688011112042f   // 0.125 * log2(e)

// ---- bf16 pack: {lo, hi} -> bf16x2 in one u32 ----
__device__ __forceinline__ uint32_t bf2(float lo, float hi) {
    uint32_t r;
    asm("cvt.rn.bf16x2.f32 %0, %1, %2;" : "=r"(r) : "f"(hi), "f"(lo));
    return r;
}

// split a float2 into bf16x2 hi part and bf16x2 residual (lo) part.
__device__ __forceinline__ void split2(float2 p, uint32_t& hi, uint32_t& lo) {
    hi = bf2(p.x, p.y);
    float h0 = __uint_as_float(hi << 16);
    float h1 = __uint_as_float(hi & 0xffff0000u);
    lo = bf2(p.x - h0, p.y - h1);
}

// ---- warp-level bf16 MMA: D(16x8,f32) += A(16x16,bf16) * B(16x8,bf16) ----
__device__ __forceinline__ void mma_bf16(float c[4], const uint32_t a[4],
                                         uint32_t b0, uint32_t b1) {
    asm volatile(
        "mma.sync.aligned.m16n8k16.row.col.f32.bf16.bf16.f32 "
        "{%0,%1,%2,%3}, {%4,%5,%6,%7}, {%8,%9}, {%0,%1,%2,%3};"
        : "+f"(c[0]), "+f"(c[1]), "+f"(c[2]), "+f"(c[3])
        : "r"(a[0]), "r"(a[1]), "r"(a[2]), "r"(a[3]), "r"(b0), "r"(b1));
}

__device__ __forceinline__ float ex2f(float x) {
    float r; asm("ex2.approx.f32 %0, %1;" : "=f"(r) : "f"(x)); return r;
}
__device__ __forceinline__ uint32_t smem_u32(const void* p) {
    uint32_t a;
    asm("{ .reg .u64 t; cvta.to.shared.u64 t, %1; cvt.u32.u64 %0, t; }" : "=r"(a) : "l"(p));
    return a;
}

#define CP_ASYNC16(dst_u32, src_ptr) \
    asm volatile("cp.async.ca.shared.global [%0], [%1], 16;" :: "r"(dst_u32), "l"(src_ptr) : "memory")
#define CP_COMMIT() asm volatile("cp.async.commit_group;" ::: "memory")
#define CP_WAIT(n)  asm volatile("cp.async.wait_group %0;" :: "n"(n) : "memory")

// ============================================================================
// Kernel 1: tensor-core projections (R12 structure, NO reg cap).
//   Q/K: plain bf16 MMA, branchless uniform nest per matrix.
//   V:   error-compensated (xh*Wh + xl*Wh + xh*Wl, err ~2^-18).
//   No __launch_bounds__ occupancy cap: lets aXl stay resident (R12's cap
//   spilled it to local and regressed).
// ============================================================================
#define PT 66   // smem transpose pitch (floats)

__global__ void __launch_bounds__(128) proj_kernel(
    const float* __restrict__ x,
    const float* __restrict__ Wq,
    const float* __restrict__ Wk,
    const float* __restrict__ Wv)
{
    __shared__ float sVt[128 * PT];   // 33792 B static

    const int tid  = threadIdx.x;
    const int lane = tid & 31;
    const int wid  = tid >> 5;
    const int lg   = lane >> 2;
    const int lt   = lane & 3;

    const int bh = blockIdx.y;
    const int b  = bh >> 4;
    const int h  = bh & 15;
    const int t0 = blockIdx.x * 128;
    const int wq = t0 + wid * 32;

    // ---- load x tile as hi/lo bf16 A-fragments (lo used only for V) ----
    uint32_t aXh[2][4][4], aXl[2][4][4];
    #pragma unroll
    for (int mt = 0; mt < 2; ++mt) {
        #pragma unroll
        for (int kj = 0; kj < 4; ++kj) {
            const int r0 = wq + mt * 16 + lg;
            const float* p = x + ((size_t)(b * Tq + r0)) * Eq + h * Dq + kj * 16 + 2 * lt;
            float2 lo0 = *(const float2*)(p);
            float2 hi0 = *(const float2*)(p + 8);
            const float* q = p + (size_t)8 * Eq;
            float2 lo1 = *(const float2*)(q);
            float2 hi1 = *(const float2*)(q + 8);
            split2(lo0, aXh[mt][kj][0], aXl[mt][kj][0]);
            split2(lo1, aXh[mt][kj][1], aXl[mt][kj][1]);
            split2(hi0, aXh[mt][kj][2], aXl[mt][kj][2]);
            split2(hi1, aXh[mt][kj][3], aXl[mt][kj][3]);
        }
    }

    // ================= Q and K: plain bf16, uniform branchless loops ========
    #pragma unroll 1
    for (int m = 0; m < 2; ++m) {
        const float* W = (m == 0) ? Wq : Wk;

        float c[2][8][4];
        #pragma unroll
        for (int mt = 0; mt < 2; ++mt)
            #pragma unroll
            for (int nt = 0; nt < 8; ++nt)
                #pragma unroll
                for (int e = 0; e < 4; ++e) c[mt][nt][e] = 0.f;

        #pragma unroll
        for (int kj = 0; kj < 4; ++kj) {
            #pragma unroll
            for (int nt = 0; nt < 8; ++nt) {
                const float* wp = W + (size_t)(nt * 8 + lg) * 64 + kj * 16 + 2 * lt;
                const uint32_t wh0 = bf2(wp[0], wp[1]);
                const uint32_t wh1 = bf2(wp[8], wp[9]);
                mma_bf16(c[0][nt], aXh[0][kj], wh0, wh1);
                mma_bf16(c[1][nt], aXh[1][kj], wh0, wh1);
            }
        }

        // ---- epilogue: bf16 with pos16 pair-permutation ----
        uint16_t* g = (m == 0 ? g_Qb : g_Kb);
        const float s = (m == 0) ? SCALE_LOG2E : 1.0f;
        #pragma unroll
        for (int mt = 0; mt < 2; ++mt) {
            const int t = wq + mt * 16 + lg;
            uint16_t* r0 = g + ((size_t)bh * Tq + t) * Dq;
            uint16_t* r1 = r0 + (size_t)8 * Dq;
            #pragma unroll
            for (int nt = 0; nt < 8; ++nt) {
                const int pos = 16 * (nt >> 1) + 4 * lt + 2 * (nt & 1);
                *(uint32_t*)(r0 + pos) = bf2(c[mt][nt][0] * s, c[mt][nt][1] * s);
                *(uint32_t*)(r1 + pos) = bf2(c[mt][nt][2] * s, c[mt][nt][3] * s);
            }
        }
    }

    // ================= V: error-compensated =================================
    {
        float c[2][8][4];
        #pragma unroll
        for (int mt = 0; mt < 2; ++mt)
            #pragma unroll
            for (int nt = 0; nt < 8; ++nt)
                #pragma unroll
                for (int e = 0; e < 4; ++e) c[mt][nt][e] = 0.f;

        #pragma unroll
        for (int kj = 0; kj < 4; ++kj) {
            #pragma unroll
            for (int nt = 0; nt < 8; ++nt) {
                const float* wp = Wv + (size_t)(nt * 8 + lg) * 64 + kj * 16 + 2 * lt;
                uint32_t wh0, wl0, wh1, wl1;
                split2(*(const float2*)(wp),     wh0, wl0);
                split2(*(const float2*)(wp + 8), wh1, wl1);
                #pragma unroll
                for (int mt = 0; mt < 2; ++mt) {
                    mma_bf16(c[mt][nt], aXh[mt][kj], wh0, wh1);
                    mma_bf16(c[mt][nt], aXl[mt][kj], wh0, wh1);
                    mma_bf16(c[mt][nt], aXh[mt][kj], wl0, wl1);
                }
            }
        }

        // ---- V epilogue: fp32 row-major + smem stage for transpose ----
        #pragma unroll
        for (int mt = 0; mt < 2; ++mt) {
            const int t    = wq + mt * 16 + lg;
            const int tloc = wid * 32 + mt * 16 + lg;
            float* r0 = g_V + ((size_t)bh * Tq + t) * Dq;
            float* r1 = r0 + (size_t)8 * Dq;
            #pragma unroll
            for (int nt = 0; nt < 8; ++nt) {
                const int col = nt * 8 + 2 * lt;
                *(float2*)(r0 + col) = make_float2(c[mt][nt][0], c[mt][nt][1]);
                *(float2*)(r1 + col) = make_float2(c[mt][nt][2], c[mt][nt][3]);
                *(float2*)(sVt + tloc * PT + col)       = make_float2(c[mt][nt][0], c[mt][nt][1]);
                *(float2*)(sVt + (tloc + 8) * PT + col) = make_float2(c[mt][nt][2], c[mt][nt][3]);
            }
        }
        __syncthreads();
        const int d    = tid >> 1;
        const int half = tid & 1;
        const float* src = sVt + half * 64 * PT + d;
        uint16_t* dst = g_Vtb + (size_t)bh * Dq * Tq + (size_t)d * Tq + t0 + half * 64;
        #pragma unroll
        for (int blk = 0; blk < 4; ++blk) {
            #pragma unroll
            for (int q = 0; q < 4; ++q) {
                const float v0 = src[(blk * 16 + 2 * q)     * PT];
                const float v1 = src[(blk * 16 + 2 * q + 1) * PT];
                const float v8 = src[(blk * 16 + 2 * q + 8) * PT];
                const float v9 = src[(blk * 16 + 2 * q + 9) * PT];
                *(uint2*)(dst + blk * 16 + 4 * q) = make_uint2(bf2(v0, v1), bf2(v8, v9));
            }
        }
    }
}

// ============================================================================
// Kernel 2: mma.sync bf16 flash attention (R9 — proven 185us, UNCHANGED).
// ============================================================================
#define QBLK 128
#define KBLK 64
#define NT   (Tq / KBLK)              // 32 tiles
#define PKB  160                      // byte pitch of K/Vt smem rows
#define TILEB (64 * PKB)              // 10240 B per tile
#define SM_BYTES (8 * TILEB)          // 4 bufs x (K + Vt) = 81920 B

__global__ void __launch_bounds__(128, 2) attn_kernel(float* __restrict__ out)
{
    extern __shared__ __align__(16) char smc[];

    const int tid  = threadIdx.x;
    const int lane = tid & 31;
    const int wid  = tid >> 5;
    const int lg   = lane >> 2;
    const int lt   = lane & 3;

    const int bh = blockIdx.y;
    const int b  = bh >> 4;
    const int h  = bh & 15;
    const int q0 = blockIdx.x * QBLK;
    const int wq = q0 + wid * 32;

    const uint32_t smb = smem_u32(smc);
    const uint16_t* gKb  = g_Kb  + (size_t)bh * Tq * Dq;
    const uint16_t* gVtb = g_Vtb + (size_t)bh * Dq * Tq;

    // ---- Q fragments: m16n8k16 A-frags ----
    uint32_t aQ[2][4][4];
    {
        const uint16_t* Qb = g_Qb + ((size_t)bh * Tq + wq) * Dq;
        #pragma unroll
        for (int mt = 0; mt < 2; ++mt) {
            #pragma unroll
            for (int kj = 0; kj < 4; ++kj) {
                const uint2 lo = *(const uint2*)(Qb + (size_t)(mt * 16 + lg) * Dq + kj * 16 + 4 * lt);
                const uint2 hi = *(const uint2*)(Qb + (size_t)(mt * 16 + lg + 8) * Dq + kj * 16 + 4 * lt);
                aQ[mt][kj][0] = lo.x;
                aQ[mt][kj][1] = hi.x;
                aQ[mt][kj][2] = lo.y;
                aQ[mt][kj][3] = hi.y;
            }
        }
    }

    float o[2][8][4];
    #pragma unroll
    for (int mt = 0; mt < 2; ++mt)
        #pragma unroll
        for (int nt = 0; nt < 8; ++nt)
            #pragma unroll
            for (int e = 0; e < 4; ++e) o[mt][nt][e] = 0.f;

    float rs[4] = {0.f, 0.f, 0.f, 0.f};

    auto stage = [&](int it, int buf) {
        const uint32_t sKu  = smb + (uint32_t)(buf * 2 * TILEB);
        const uint32_t sVtu = sKu + (uint32_t)TILEB;
        const uint16_t* gk = gKb + (size_t)it * KBLK * Dq;
        const int s0 = it * KBLK;
        #pragma unroll
        for (int j = 0; j < 4; ++j) {
            const int f = tid + 128 * j;
            const int r = f >> 3, i = f & 7;
            CP_ASYNC16(sKu + (uint32_t)(r * PKB + 16 * i), gk + (size_t)r * Dq + 8 * i);
            CP_ASYNC16(sVtu + (uint32_t)(r * PKB + 16 * i), gVtb + (size_t)r * Tq + s0 + 8 * i);
        }
    };

    stage(0, 0); CP_COMMIT();
    stage(1, 1); CP_COMMIT();

    #pragma unroll 1
    for (int it = 0; it < NT; ++it) {
        if (it + 2 < NT) {
            stage(it + 2, (it + 2) & 3);
            CP_COMMIT();
            CP_WAIT(2);
        } else if (it + 1 < NT) {
            CP_WAIT(1);
        } else {
            CP_WAIT(0);
        }
        __syncthreads();

        const char* sK  = smc + (it & 3) * 2 * TILEB;
        const char* sVt = sK + TILEB;

        // ---- QK^T ----
        float c[2][8][4];
        #pragma unroll
        for (int mt = 0; mt < 2; ++mt)
            #pragma unroll
            for (int nt = 0; nt < 8; ++nt)
                #pragma unroll
                for (int e = 0; e < 4; ++e) c[mt][nt][e] = 0.f;

        #pragma unroll
        for (int kj = 0; kj < 4; ++kj) {
            #pragma unroll
            for (int nt = 0; nt < 8; ++nt) {
                const uint2 bv = *(const uint2*)(sK + (nt * 8 + lg) * PKB + 32 * kj + 8 * lt);
                mma_bf16(c[0][nt], aQ[0][kj], bv.x, bv.y);
                mma_bf16(c[1][nt], aQ[1][kj], bv.x, bv.y);
            }
        }

        // ---- exp (pipelined into PV) + PV ----
        #define EXPP(jj) do { \
            _Pragma("unroll") \
            for (int mt = 0; mt < 2; ++mt) { \
                _Pragma("unroll") \
                for (int hh = 0; hh < 2; ++hh) { \
                    float* cc = c[mt][2 * (jj) + hh]; \
                    float p0 = ex2f(cc[0]); \
                    float p1 = ex2f(cc[1]); \
                    float p2 = ex2f(cc[2]); \
                    float p3 = ex2f(cc[3]); \
                    rs[mt * 2 + 0] += p0 + p1; \
                    rs[mt * 2 + 1] += p2 + p3; \
                    cc[0] = p0; cc[1] = p1; cc[2] = p2; cc[3] = p3; \
                } \
            } \
        } while (0)

        EXPP(0);
        #pragma unroll
        for (int j = 0; j < 4; ++j) {
            if (j < 3) EXPP(j + 1);
            uint32_t aP0[4], aP1[4];
            aP0[0] = bf2(c[0][2*j][0],   c[0][2*j][1]);
            aP0[1] = bf2(c[0][2*j][2],   c[0][2*j][3]);
            aP0[2] = bf2(c[0][2*j+1][0], c[0][2*j+1][1]);
            aP0[3] = bf2(c[0][2*j+1][2], c[0][2*j+1][3]);
            aP1[0] = bf2(c[1][2*j][0],   c[1][2*j][1]);
            aP1[1] = bf2(c[1][2*j][2],   c[1][2*j][3]);
            aP1[2] = bf2(c[1][2*j+1][0], c[1][2*j+1][1]);
            aP1[3] = bf2(c[1][2*j+1][2], c[1][2*j+1][3]);
            #pragma unroll
            for (int nt = 0; nt < 8; ++nt) {
                const uint2 bv = *(const uint2*)(sVt + (nt * 8 + lg) * PKB + 32 * j + 8 * lt);
                mma_bf16(o[0][nt], aP0, bv.x, bv.y);
                mma_bf16(o[1][nt], aP1, bv.x, bv.y);
            }
        }
        #undef EXPP
    }

    // ---- row sums ----
    float inv[4];
    #pragma unroll
    for (int i = 0; i < 4; ++i) {
        float v = rs[i];
        v += __shfl_xor_sync(0xffffffffu, v, 1);
        v += __shfl_xor_sync(0xffffffffu, v, 2);
        inv[i] = 1.f / v;
    }

    // ---- epilogue: O/l + V residual (fp32) -> out[b, t, h*64 + d] ----
    #pragma unroll
    for (int mt = 0; mt < 2; ++mt) {
        #pragma unroll
        for (int half = 0; half < 2; ++half) {
            const int t  = wq + mt * 16 + half * 8 + lg;
            const float iv = inv[mt * 2 + half];
            const float2* vr = (const float2*)(g_V + ((size_t)bh * Tq + t) * Dq);
            float2* op = (float2*)(out + ((size_t)(b * Tq + t)) * Eq + h * Dq);
            #pragma unroll
            for (int nt = 0; nt < 8; ++nt) {
                const int idx = nt * 4 + lt;
                float2 v = vr[idx];
                op[idx] = make_float2(o[mt][nt][half * 2 + 0] * iv + v.x,
                                      o[mt][nt][half * 2 + 1] * iv + v.y);
            }
        }
    }
}

// ============================================================================
extern "C" void kernel_launch(void* const* d_in, const int* in_sizes, int n_in,
                              void* d_out, int out_size)
{
    const float* x  = (const float*)d_in[0];
    const float* Wq = (const float*)d_in[1];
    const float* Wk = (const float*)d_in[2];
    const float* Wv = (const float*)d_in[3];
    float* out = (float*)d_out;

    cudaFuncSetAttribute(attn_kernel, cudaFuncAttributeMaxDynamicSharedMemorySize, SM_BYTES);

    dim3 pgrid(Tq / 128, BHq);
    proj_kernel<<<pgrid, 128>>>(x, Wq, Wk, Wv);

    dim3 agrid(Tq / QBLK, BHq);
    attn_kernel<<<agrid, 128, SM_BYTES>>>(out);
}

// round 14
// speedup vs baseline: 1.1730x; 1.0547x over previous
#include <cuda_runtime.h>
#include <math.h>
#include <stdint.h>

// Problem constants
#define Bq   4
#define Tq   2048
#define Eq   1024
#define Hq   16
#define Dq   64
#define BHq  (Bq*Hq)

// Scratch (alloc-free rule: static __device__ arrays).
__device__ uint16_t g_Qb [(size_t)BHq * Tq * Dq];  // bf16, d pair-permuted, pre-scaled
__device__ uint16_t g_Kb [(size_t)BHq * Tq * Dq];  // bf16, d pair-permuted
__device__ float    g_V  [(size_t)BHq * Tq * Dq];  // fp32 row-major (exact residual)
__device__ uint16_t g_Vtb[(size_t)BHq * Dq * Tq];  // bf16, transposed, t pair-permuted

#define SCALE_LOG2E 0.18033688011112042f   // 0.125 * log2(e)

// ---- bf16 pack: {lo, hi} -> bf16x2 in one u32 ----
__device__ __forceinline__ uint32_t bf2(float lo, float hi) {
    uint32_t r;
    asm("cvt.rn.bf16x2.f32 %0, %1, %2;" : "=r"(r) : "f"(hi), "f"(lo));
    return r;
}

// split a float2 into bf16x2 hi part and bf16x2 residual (lo) part.
__device__ __forceinline__ void split2(float2 p, uint32_t& hi, uint32_t& lo) {
    hi = bf2(p.x, p.y);
    float h0 = __uint_as_float(hi << 16);
    float h1 = __uint_as_float(hi & 0xffff0000u);
    lo = bf2(p.x - h0, p.y - h1);
}

// ---- warp-level bf16 MMA: D(16x8,f32) += A(16x16,bf16) * B(16x8,bf16) ----
__device__ __forceinline__ void mma_bf16(float c[4], const uint32_t a[4],
                                         uint32_t b0, uint32_t b1) {
    asm volatile(
        "mma.sync.aligned.m16n8k16.row.col.f32.bf16.bf16.f32 "
        "{%0,%1,%2,%3}, {%4,%5,%6,%7}, {%8,%9}, {%0,%1,%2,%3};"
        : "+f"(c[0]), "+f"(c[1]), "+f"(c[2]), "+f"(c[3])
        : "r"(a[0]), "r"(a[1]), "r"(a[2]), "r"(a[3]), "r"(b0), "r"(b1));
}

__device__ __forceinline__ float ex2f(float x) {
    float r; asm("ex2.approx.f32 %0, %1;" : "=f"(r) : "f"(x)); return r;
}
__device__ __forceinline__ uint32_t smem_u32(const void* p) {
    uint32_t a;
    asm("{ .reg .u64 t; cvta.to.shared.u64 t, %1; cvt.u32.u64 %0, t; }" : "=r"(a) : "l"(p));
    return a;
}

#define CP_ASYNC16(dst_u32, src_ptr) \
    asm volatile("cp.async.ca.shared.global [%0], [%1], 16;" :: "r"(dst_u32), "l"(src_ptr) : "memory")
#define CP_COMMIT() asm volatile("cp.async.commit_group;" ::: "memory")
#define CP_WAIT(n)  asm volatile("cp.async.wait_group %0;" :: "n"(n) : "memory")

// ============================================================================
// Kernel 1: tensor-core projections with error-compensated bf16 (R9 verbatim
// — proven 62us). Single uniform m-loop: C = xh*Wh + xl*Wh + xh*Wl.
// ============================================================================
#define PT 66   // smem transpose pitch (floats)

__global__ void __launch_bounds__(128) proj_kernel(
    const float* __restrict__ x,
    const float* __restrict__ Wq,
    const float* __restrict__ Wk,
    const float* __restrict__ Wv)
{
    __shared__ float sVt[128 * PT];

    const int tid  = threadIdx.x;
    const int lane = tid & 31;
    const int wid  = tid >> 5;
    const int lg   = lane >> 2;
    const int lt   = lane & 3;

    const int bh = blockIdx.y;
    const int b  = bh >> 4;
    const int h  = bh & 15;
    const int t0 = blockIdx.x * 128;
    const int wq = t0 + wid * 32;

    // ---- load x tile as hi/lo bf16 A-fragments ----
    uint32_t aXh[2][4][4], aXl[2][4][4];
    #pragma unroll
    for (int mt = 0; mt < 2; ++mt) {
        #pragma unroll
        for (int kj = 0; kj < 4; ++kj) {
            const int r0 = wq + mt * 16 + lg;
            const float* p = x + ((size_t)(b * Tq + r0)) * Eq + h * Dq + kj * 16 + 2 * lt;
            float2 lo0 = *(const float2*)(p);
            float2 hi0 = *(const float2*)(p + 8);
            const float* q = p + (size_t)8 * Eq;
            float2 lo1 = *(const float2*)(q);
            float2 hi1 = *(const float2*)(q + 8);
            split2(lo0, aXh[mt][kj][0], aXl[mt][kj][0]);
            split2(lo1, aXh[mt][kj][1], aXl[mt][kj][1]);
            split2(hi0, aXh[mt][kj][2], aXl[mt][kj][2]);
            split2(hi1, aXh[mt][kj][3], aXl[mt][kj][3]);
        }
    }

    #pragma unroll 1
    for (int m = 0; m < 3; ++m) {
        const float* W = (m == 0) ? Wq : ((m == 1) ? Wk : Wv);

        float c[2][8][4];
        #pragma unroll
        for (int mt = 0; mt < 2; ++mt)
            #pragma unroll
            for (int nt = 0; nt < 8; ++nt)
                #pragma unroll
                for (int e = 0; e < 4; ++e) c[mt][nt][e] = 0.f;

        #pragma unroll
        for (int kj = 0; kj < 4; ++kj) {
            #pragma unroll
            for (int nt = 0; nt < 8; ++nt) {
                const float* wp = W + (size_t)(nt * 8 + lg) * 64 + kj * 16 + 2 * lt;
                uint32_t wh0, wl0, wh1, wl1;
                split2(*(const float2*)(wp),     wh0, wl0);
                split2(*(const float2*)(wp + 8), wh1, wl1);
                #pragma unroll
                for (int mt = 0; mt < 2; ++mt) {
                    mma_bf16(c[mt][nt], aXh[mt][kj], wh0, wh1);
                    mma_bf16(c[mt][nt], aXl[mt][kj], wh0, wh1);
                    mma_bf16(c[mt][nt], aXh[mt][kj], wl0, wl1);
                }
            }
        }

        if (m < 2) {
            uint16_t* g = (m == 0 ? g_Qb : g_Kb);
            const float s = (m == 0) ? SCALE_LOG2E : 1.0f;
            #pragma unroll
            for (int mt = 0; mt < 2; ++mt) {
                const int t = wq + mt * 16 + lg;
                uint16_t* r0 = g + ((size_t)bh * Tq + t) * Dq;
                uint16_t* r1 = r0 + (size_t)8 * Dq;
                #pragma unroll
                for (int nt = 0; nt < 8; ++nt) {
                    const int pos = 16 * (nt >> 1) + 4 * lt + 2 * (nt & 1);
                    *(uint32_t*)(r0 + pos) = bf2(c[mt][nt][0] * s, c[mt][nt][1] * s);
                    *(uint32_t*)(r1 + pos) = bf2(c[mt][nt][2] * s, c[mt][nt][3] * s);
                }
            }
        } else {
            #pragma unroll
            for (int mt = 0; mt < 2; ++mt) {
                const int t    = wq + mt * 16 + lg;
                const int tloc = wid * 32 + mt * 16 + lg;
                float* r0 = g_V + ((size_t)bh * Tq + t) * Dq;
                float* r1 = r0 + (size_t)8 * Dq;
                #pragma unroll
                for (int nt = 0; nt < 8; ++nt) {
                    const int col = nt * 8 + 2 * lt;
                    *(float2*)(r0 + col) = make_float2(c[mt][nt][0], c[mt][nt][1]);
                    *(float2*)(r1 + col) = make_float2(c[mt][nt][2], c[mt][nt][3]);
                    *(float2*)(sVt + tloc * PT + col)       = make_float2(c[mt][nt][0], c[mt][nt][1]);
                    *(float2*)(sVt + (tloc + 8) * PT + col) = make_float2(c[mt][nt][2], c[mt][nt][3]);
                }
            }
            __syncthreads();
            const int d    = tid >> 1;
            const int half = tid & 1;
            const float* src = sVt + half * 64 * PT + d;
            uint16_t* dst = g_Vtb + (size_t)bh * Dq * Tq + (size_t)d * Tq + t0 + half * 64;
            #pragma unroll
            for (int blk = 0; blk < 4; ++blk) {
                #pragma unroll
                for (int q = 0; q < 4; ++q) {
                    const float v0 = src[(blk * 16 + 2 * q)     * PT];
                    const float v1 = src[(blk * 16 + 2 * q + 1) * PT];
                    const float v8 = src[(blk * 16 + 2 * q + 8) * PT];
                    const float v9 = src[(blk * 16 + 2 * q + 9) * PT];
                    *(uint2*)(dst + blk * 16 + 4 * q) = make_uint2(bf2(v0, v1), bf2(v8, v9));
                }
            }
        }
    }
}

// ============================================================================
// Kernel 2: mma.sync bf16 flash attention — MUFU/HMMA interleave edition.
//   Tile body reordered: QK_A -> {QK_B || exp_A} -> {PV_A || exp_B} -> PV_B
//   so the 64 per-warp exps issue inside HMMA phases instead of serializing.
// ============================================================================
#define QBLK 128
#define KBLK 64
#define NT   (Tq / KBLK)              // 32 tiles
#define PKB  160                      // byte pitch of K/Vt smem rows
#define TILEB (64 * PKB)              // 10240 B per tile
#define SM_BYTES (8 * TILEB)          // 4 bufs x (K + Vt) = 81920 B

__global__ void __launch_bounds__(128, 2) attn_kernel(float* __restrict__ out)
{
    extern __shared__ __align__(16) char smc[];

    const int tid  = threadIdx.x;
    const int lane = tid & 31;
    const int wid  = tid >> 5;
    const int lg   = lane >> 2;
    const int lt   = lane & 3;

    const int bh = blockIdx.y;
    const int b  = bh >> 4;
    const int h  = bh & 15;
    const int q0 = blockIdx.x * QBLK;
    const int wq = q0 + wid * 32;

    const uint32_t smb = smem_u32(smc);
    const uint16_t* gKb  = g_Kb  + (size_t)bh * Tq * Dq;
    const uint16_t* gVtb = g_Vtb + (size_t)bh * Dq * Tq;

    // ---- Q fragments ----
    uint32_t aQ[2][4][4];
    {
        const uint16_t* Qb = g_Qb + ((size_t)bh * Tq + wq) * Dq;
        #pragma unroll
        for (int mt = 0; mt < 2; ++mt) {
            #pragma unroll
            for (int kj = 0; kj < 4; ++kj) {
                const uint2 lo = *(const uint2*)(Qb + (size_t)(mt * 16 + lg) * Dq + kj * 16 + 4 * lt);
                const uint2 hi = *(const uint2*)(Qb + (size_t)(mt * 16 + lg + 8) * Dq + kj * 16 + 4 * lt);
                aQ[mt][kj][0] = lo.x;
                aQ[mt][kj][1] = hi.x;
                aQ[mt][kj][2] = lo.y;
                aQ[mt][kj][3] = hi.y;
            }
        }
    }

    float o[2][8][4];
    #pragma unroll
    for (int mt = 0; mt < 2; ++mt)
        #pragma unroll
        for (int nt = 0; nt < 8; ++nt)
            #pragma unroll
            for (int e = 0; e < 4; ++e) o[mt][nt][e] = 0.f;

    float rs[4] = {0.f, 0.f, 0.f, 0.f};

    auto stage = [&](int it, int buf) {
        const uint32_t sKu  = smb + (uint32_t)(buf * 2 * TILEB);
        const uint32_t sVtu = sKu + (uint32_t)TILEB;
        const uint16_t* gk = gKb + (size_t)it * KBLK * Dq;
        const int s0 = it * KBLK;
        #pragma unroll
        for (int j = 0; j < 4; ++j) {
            const int f = tid + 128 * j;
            const int r = f >> 3, i = f & 7;
            CP_ASYNC16(sKu + (uint32_t)(r * PKB + 16 * i), gk + (size_t)r * Dq + 8 * i);
            CP_ASYNC16(sVtu + (uint32_t)(r * PKB + 16 * i), gVtb + (size_t)r * Tq + s0 + 8 * i);
        }
    };

    stage(0, 0); CP_COMMIT();
    stage(1, 1); CP_COMMIT();

    // exp one C-fragment group (4 values) + accumulate row sums
    #define EXP1(mt, idx) do { \
        float* cc = c[mt][idx]; \
        float p0 = ex2f(cc[0]); \
        float p1 = ex2f(cc[1]); \
        float p2 = ex2f(cc[2]); \
        float p3 = ex2f(cc[3]); \
        rs[(mt) * 2 + 0] += p0 + p1; \
        rs[(mt) * 2 + 1] += p2 + p3; \
        cc[0] = p0; cc[1] = p1; cc[2] = p2; cc[3] = p3; \
    } while (0)

    #pragma unroll 1
    for (int it = 0; it < NT; ++it) {
        if (it + 2 < NT) {
            stage(it + 2, (it + 2) & 3);
            CP_COMMIT();
            CP_WAIT(2);
        } else if (it + 1 < NT) {
            CP_WAIT(1);
        } else {
            CP_WAIT(0);
        }
        __syncthreads();

        const char* sK  = smc + (it & 3) * 2 * TILEB;
        const char* sVt = sK + TILEB;

        float c[2][8][4];
        #pragma unroll
        for (int mt = 0; mt < 2; ++mt)
            #pragma unroll
            for (int nt = 0; nt < 8; ++nt)
                #pragma unroll
                for (int e = 0; e < 4; ++e) c[mt][nt][e] = 0.f;

        // ---- Phase 1: QK for A half (nt 0..3) ----
        #pragma unroll
        for (int kj = 0; kj < 4; ++kj) {
            #pragma unroll
            for (int nt = 0; nt < 4; ++nt) {
                const uint2 bv = *(const uint2*)(sK + (nt * 8 + lg) * PKB + 32 * kj + 8 * lt);
                mma_bf16(c[0][nt], aQ[0][kj], bv.x, bv.y);
                mma_bf16(c[1][nt], aQ[1][kj], bv.x, bv.y);
            }
        }

        // ---- Phase 2: QK for B half (nt 4..7) interleaved with exp_A ----
        #pragma unroll
        for (int kj = 0; kj < 4; ++kj) {
            EXP1(0, kj);                 // MUFU: exp A-group fragment kj
            #pragma unroll
            for (int nt = 4; nt < 8; ++nt) {
                const uint2 bv = *(const uint2*)(sK + (nt * 8 + lg) * PKB + 32 * kj + 8 * lt);
                mma_bf16(c[0][nt], aQ[0][kj], bv.x, bv.y);
                mma_bf16(c[1][nt], aQ[1][kj], bv.x, bv.y);
            }
            EXP1(1, kj);
        }

        // ---- Phase 3: PV for A (j=0,1) interleaved with exp_B ----
        #pragma unroll
        for (int j = 0; j < 2; ++j) {
            EXP1(0, 4 + 2 * j);          // MUFU: exp B-group fragments
            EXP1(1, 4 + 2 * j);
            uint32_t aP0[4], aP1[4];
            aP0[0] = bf2(c[0][2*j][0],   c[0][2*j][1]);
            aP0[1] = bf2(c[0][2*j][2],   c[0][2*j][3]);
            aP0[2] = bf2(c[0][2*j+1][0], c[0][2*j+1][1]);
            aP0[3] = bf2(c[0][2*j+1][2], c[0][2*j+1][3]);
            aP1[0] = bf2(c[1][2*j][0],   c[1][2*j][1]);
            aP1[1] = bf2(c[1][2*j][2],   c[1][2*j][3]);
            aP1[2] = bf2(c[1][2*j+1][0], c[1][2*j+1][1]);
            aP1[3] = bf2(c[1][2*j+1][2], c[1][2*j+1][3]);
            EXP1(0, 5 + 2 * j);
            EXP1(1, 5 + 2 * j);
            #pragma unroll
            for (int nt = 0; nt < 8; ++nt) {
                const uint2 bv = *(const uint2*)(sVt + (nt * 8 + lg) * PKB + 32 * j + 8 * lt);
                mma_bf16(o[0][nt], aP0, bv.x, bv.y);
                mma_bf16(o[1][nt], aP1, bv.x, bv.y);
            }
        }

        // ---- Phase 4: PV for B (j=2,3) ----
        #pragma unroll
        for (int j = 2; j < 4; ++j) {
            uint32_t aP0[4], aP1[4];
            aP0[0] = bf2(c[0][2*j][0],   c[0][2*j][1]);
            aP0[1] = bf2(c[0][2*j][2],   c[0][2*j][3]);
            aP0[2] = bf2(c[0][2*j+1][0], c[0][2*j+1][1]);
            aP0[3] = bf2(c[0][2*j+1][2], c[0][2*j+1][3]);
            aP1[0] = bf2(c[1][2*j][0],   c[1][2*j][1]);
            aP1[1] = bf2(c[1][2*j][2],   c[1][2*j][3]);
            aP1[2] = bf2(c[1][2*j+1][0], c[1][2*j+1][1]);
            aP1[3] = bf2(c[1][2*j+1][2], c[1][2*j+1][3]);
            #pragma unroll
            for (int nt = 0; nt < 8; ++nt) {
                const uint2 bv = *(const uint2*)(sVt + (nt * 8 + lg) * PKB + 32 * j + 8 * lt);
                mma_bf16(o[0][nt], aP0, bv.x, bv.y);
                mma_bf16(o[1][nt], aP1, bv.x, bv.y);
            }
        }
    }
    #undef EXP1

    // ---- row sums ----
    float inv[4];
    #pragma unroll
    for (int i = 0; i < 4; ++i) {
        float v = rs[i];
        v += __shfl_xor_sync(0xffffffffu, v, 1);
        v += __shfl_xor_sync(0xffffffffu, v, 2);
        inv[i] = 1.f / v;
    }

    // ---- epilogue: O/l + V residual (fp32) -> out[b, t, h*64 + d] ----
    #pragma unroll
    for (int mt = 0; mt < 2; ++mt) {
        #pragma unroll
        for (int half = 0; half < 2; ++half) {
            const int t  = wq + mt * 16 + half * 8 + lg;
            const float iv = inv[mt * 2 + half];
            const float2* vr = (const float2*)(g_V + ((size_t)bh * Tq + t) * Dq);
            float2* op = (float2*)(out + ((size_t)(b * Tq + t)) * Eq + h * Dq);
            #pragma unroll
            for (int nt = 0; nt < 8; ++nt) {
                const int idx = nt * 4 + lt;
                float2 v = vr[idx];
                op[idx] = make_float2(o[mt][nt][half * 2 + 0] * iv + v.x,
                                      o[mt][nt][half * 2 + 1] * iv + v.y);
            }
        }
    }
}

// ============================================================================
extern "C" void kernel_launch(void* const* d_in, const int* in_sizes, int n_in,
                              void* d_out, int out_size)
{
    const float* x  = (const float*)d_in[0];
    const float* Wq = (const float*)d_in[1];
    const float* Wk = (const float*)d_in[2];
    const float* Wv = (const float*)d_in[3];
    float* out = (float*)d_out;

    cudaFuncSetAttribute(attn_kernel, cudaFuncAttributeMaxDynamicSharedMemorySize, SM_BYTES);

    dim3 pgrid(Tq / 128, BHq);
    proj_kernel<<<pgrid, 128>>>(x, Wq, Wk, Wv);

    dim3 agrid(Tq / QBLK, BHq);
    attn_kernel<<<agrid, 128, SM_BYTES>>>(out);
}